// round 7
// baseline (speedup 1.0000x reference)
#include <cuda_runtime.h>

// EMD / min-permutation matching on GB300.
//   B=32768, N=6, D=64.
//   cost[b] = (sum sq norms) - 2 * maxAssign(G),  G[n][m] = p_n . t_m
//   out[0] = sum_b cost[b]
//
// R7 = R6 (8 lanes/batch, direct LDG, smem re-partition tail)
//      + packed fp32 math: fma.rn.f32x2 halves the Gram FMA issue count
//        (ptxas never emits FFMA2 from C++; PTX-only).

#define BLOCK   128
#define SLOT    44    // 36 G + 1 sq + 7 pad; 44 % 32 == 12 -> STS.128 conflict-free

typedef unsigned long long u64t;

__device__ __forceinline__ u64t pk2(float lo, float hi) {
    u64t r; asm("mov.b64 %0, {%1, %2};" : "=l"(r) : "f"(lo), "f"(hi)); return r;
}
__device__ __forceinline__ float2 unpk2(u64t v) {
    float2 f; asm("mov.b64 {%0, %1}, %2;" : "=f"(f.x), "=f"(f.y) : "l"(v)); return f;
}
__device__ __forceinline__ u64t mul2(u64t a, u64t b) {
    u64t d; asm("mul.rn.f32x2 %0, %1, %2;" : "=l"(d) : "l"(a), "l"(b)); return d;
}
__device__ __forceinline__ u64t fma2(u64t a, u64t b, u64t c) {
    u64t d; asm("fma.rn.f32x2 %0, %1, %2, %3;" : "=l"(d) : "l"(a), "l"(b), "l"(c)); return d;
}

__global__ __launch_bounds__(BLOCK, 5)
void emd_kernel(const float* __restrict__ preds,
                const float* __restrict__ targets,
                float* __restrict__ out, int B)
{
    __shared__ float sh[BLOCK * SLOT];    // 22528 B

    const int t    = threadIdx.x;
    const int g    = blockIdx.x * BLOCK + t;
    const int bRaw = g >> 3;          // batch index
    const int j    = g & 7;           // lane within 8-thread group
    const int b = (bRaw < B) ? bRaw : (B - 1);   // clamp keeps lanes converged

    const float* pp = preds   + (size_t)b * 384 + 4 * j;
    const float* tt = targets + (size_t)b * 384 + 4 * j;

    // ---- 1) 12 pred loads front-batched, packed into f32x2 pairs
    u64t paxy[6], pazw[6], pcxy[6], pczw[6];
#pragma unroll
    for (int n = 0; n < 6; ++n) {
        float4 a = *(const float4*)(pp + n * 64);
        float4 c = *(const float4*)(pp + n * 64 + 32);
        paxy[n] = pk2(a.x, a.y);  pazw[n] = pk2(a.z, a.w);
        pcxy[n] = pk2(c.x, c.y);  pczw[n] = pk2(c.z, c.w);
    }

    // packed sq accumulator over pred rows
    u64t sq2 = mul2(paxy[0], paxy[0]);
    sq2 = fma2(pazw[0], pazw[0], sq2);
    sq2 = fma2(pcxy[0], pcxy[0], sq2);
    sq2 = fma2(pczw[0], pczw[0], sq2);
#pragma unroll
    for (int n = 1; n < 6; ++n) {
        sq2 = fma2(paxy[n], paxy[n], sq2);
        sq2 = fma2(pazw[n], pazw[n], sq2);
        sq2 = fma2(pcxy[n], pcxy[n], sq2);
        sq2 = fma2(pczw[n], pczw[n], sq2);
    }

    float G[36];

    // ---- 2) stream target rows; packed Gram accumulation
#pragma unroll
    for (int m = 0; m < 6; ++m) {
        float4 a = *(const float4*)(tt + m * 64);
        float4 c = *(const float4*)(tt + m * 64 + 32);
        u64t qaxy = pk2(a.x, a.y), qazw = pk2(a.z, a.w);
        u64t qcxy = pk2(c.x, c.y), qczw = pk2(c.z, c.w);

        sq2 = fma2(qaxy, qaxy, sq2);
        sq2 = fma2(qazw, qazw, sq2);
        sq2 = fma2(qcxy, qcxy, sq2);
        sq2 = fma2(qczw, qczw, sq2);

#pragma unroll
        for (int n = 0; n < 6; ++n) {
            u64t acc = mul2(paxy[n], qaxy);
            acc = fma2(pazw[n], qazw, acc);
            acc = fma2(pcxy[n], qcxy, acc);
            acc = fma2(pczw[n], qczw, acc);
            float2 r = unpk2(acc);
            G[n * 6 + m] = r.x + r.y;
        }
    }
    float2 sqp = unpk2(sq2);
    const float sq = sqp.x + sqp.y;

    // ---- 3) write partial (G, sq) to own slot; STS.128, conflict-free
    {
        float* slot = &sh[t * SLOT];
#pragma unroll
        for (int i = 0; i < 9; ++i)
            *(float4*)&slot[4 * i] = make_float4(G[4*i], G[4*i+1], G[4*i+2], G[4*i+3]);
        slot[36] = sq;
    }
    __syncthreads();

    // ---- 4) one thread per batch: sum 8 partials, run DP
    float cost = 0.0f;
    if (t < BLOCK / 8) {                         // 16 batches per CTA
        const int bOut = blockIdx.x * (BLOCK / 8) + t;
        float A[37];
#pragma unroll
        for (int i = 0; i < 37; ++i) A[i] = 0.0f;

#pragma unroll
        for (int l = 0; l < 8; ++l) {
            const int rot = (l + t) & 7;                 // de-conflict rotation
            const float* slot = &sh[(t * 8 + rot) * SLOT];
#pragma unroll
            for (int e = 0; e < 9; ++e) {
                float4 v = *(const float4*)&slot[4 * e];
                A[4*e]   += v.x;  A[4*e+1] += v.y;
                A[4*e+2] += v.z;  A[4*e+3] += v.w;
            }
            A[36] += slot[36];
        }

        if (bOut < B) {
            float dp[64];
            dp[0] = 0.0f;
#pragma unroll
            for (int k = 1; k <= 6; ++k) {
                const int r = k - 1;
#pragma unroll
                for (int S = 1; S < 64; ++S) {
                    if (__popc((unsigned)S) == k) {
                        float best = -3.0e38f;
#pragma unroll
                        for (int m = 0; m < 6; ++m)
                            if (S & (1 << m))
                                best = fmaxf(best, dp[S ^ (1 << m)] + A[r * 6 + m]);
                        dp[S] = best;
                    }
                }
            }
            cost = A[36] - 2.0f * dp[63];
        }
    }

    // ---- 5) reduce the 16 costs (first warp) and atomicAdd once
    if (t < 32) {
#pragma unroll
        for (int o = 8; o > 0; o >>= 1)
            cost += __shfl_down_sync(0xffffffffu, cost, o);
        if (t == 0) atomicAdd(out, cost);
    }
}

extern "C" void kernel_launch(void* const* d_in, const int* in_sizes, int n_in,
                              void* d_out, int out_size)
{
    const float* preds   = (const float*)d_in[0];
    const float* targets = (const float*)d_in[1];
    const int B = in_sizes[0] / 384;   // 6 * 64 floats per batch

    cudaMemsetAsync(d_out, 0, sizeof(float));
    const long long threads = (long long)B * 8;
    const int grid = (int)((threads + BLOCK - 1) / BLOCK);
    emd_kernel<<<grid, BLOCK>>>(preds, targets, (float*)d_out, B);
}

// round 8
// speedup vs baseline: 1.2123x; 1.2123x over previous
#include <cuda_runtime.h>

// EMD / min-permutation matching on GB300.
//   B=32768, N=6, D=64.
//   cost[b] = (sum sq norms) - 2 * maxAssign(G),  G[n][m] = p_n . t_m
//   out[0] = sum_b cost[b]
//
// R8 = R6 tail (smem re-partition + one-thread-per-batch DP)
//      + ALL 24 loads (12 pred + 12 target) front-batched into registers
//        before any compute. ~150 regs, 3 CTA/SM: trade occupancy for
//        per-warp MLP so the only latency exposure is one wait per round.

#define BLOCK   128
#define SLOT    44    // 36 G + 1 sq + 7 pad; 44 % 32 == 12 -> STS.128 conflict-free

__global__ __launch_bounds__(BLOCK, 3)
void emd_kernel(const float* __restrict__ preds,
                const float* __restrict__ targets,
                float* __restrict__ out, int B)
{
    __shared__ float sh[BLOCK * SLOT];    // 22528 B

    const int t    = threadIdx.x;
    const int g    = blockIdx.x * BLOCK + t;
    const int bRaw = g >> 3;          // batch index
    const int j    = g & 7;           // lane within 8-thread group
    const int b = (bRaw < B) ? bRaw : (B - 1);   // clamp keeps lanes converged

    const float* pp = preds   + (size_t)b * 384 + 4 * j;
    const float* tt = targets + (size_t)b * 384 + 4 * j;

    // ---- 1) ALL 24 loads issued before any consumer (max MLP)
    float4 pa[6], pc[6], qa[6], qc[6];
#pragma unroll
    for (int n = 0; n < 6; ++n) {
        pa[n] = *(const float4*)(pp + n * 64);
        pc[n] = *(const float4*)(pp + n * 64 + 32);
    }
#pragma unroll
    for (int m = 0; m < 6; ++m) {
        qa[m] = *(const float4*)(tt + m * 64);
        qc[m] = *(const float4*)(tt + m * 64 + 32);
    }

    // ---- 2) compute: squared norms + partial Gram, all register-resident
    float sq = 0.0f;
#pragma unroll
    for (int n = 0; n < 6; ++n) {
        sq += pa[n].x*pa[n].x + pa[n].y*pa[n].y + pa[n].z*pa[n].z + pa[n].w*pa[n].w;
        sq += pc[n].x*pc[n].x + pc[n].y*pc[n].y + pc[n].z*pc[n].z + pc[n].w*pc[n].w;
    }
#pragma unroll
    for (int m = 0; m < 6; ++m) {
        sq += qa[m].x*qa[m].x + qa[m].y*qa[m].y + qa[m].z*qa[m].z + qa[m].w*qa[m].w;
        sq += qc[m].x*qc[m].x + qc[m].y*qc[m].y + qc[m].z*qc[m].z + qc[m].w*qc[m].w;
    }

    float G[36];
#pragma unroll
    for (int m = 0; m < 6; ++m) {
#pragma unroll
        for (int n = 0; n < 6; ++n) {
            G[n * 6 + m] = pa[n].x*qa[m].x + pa[n].y*qa[m].y
                         + pa[n].z*qa[m].z + pa[n].w*qa[m].w
                         + pc[n].x*qc[m].x + pc[n].y*qc[m].y
                         + pc[n].z*qc[m].z + pc[n].w*qc[m].w;
        }
    }

    // ---- 3) write partial (G, sq) to own slot; STS.128, conflict-free
    {
        float* slot = &sh[t * SLOT];
#pragma unroll
        for (int i = 0; i < 9; ++i)
            *(float4*)&slot[4 * i] = make_float4(G[4*i], G[4*i+1], G[4*i+2], G[4*i+3]);
        slot[36] = sq;
    }
    __syncthreads();

    // ---- 4) one thread per batch: sum 8 partials, run DP
    float cost = 0.0f;
    if (t < BLOCK / 8) {                         // 16 batches per CTA
        const int bOut = blockIdx.x * (BLOCK / 8) + t;
        float A[37];
#pragma unroll
        for (int i = 0; i < 37; ++i) A[i] = 0.0f;

#pragma unroll
        for (int l = 0; l < 8; ++l) {
            const int rot = (l + t) & 7;                 // de-conflict rotation
            const float* slot = &sh[(t * 8 + rot) * SLOT];
#pragma unroll
            for (int e = 0; e < 9; ++e) {
                float4 v = *(const float4*)&slot[4 * e];
                A[4*e]   += v.x;  A[4*e+1] += v.y;
                A[4*e+2] += v.z;  A[4*e+3] += v.w;
            }
            A[36] += slot[36];
        }

        if (bOut < B) {
            float dp[64];
            dp[0] = 0.0f;
#pragma unroll
            for (int k = 1; k <= 6; ++k) {
                const int r = k - 1;
#pragma unroll
                for (int S = 1; S < 64; ++S) {
                    if (__popc((unsigned)S) == k) {
                        float best = -3.0e38f;
#pragma unroll
                        for (int m = 0; m < 6; ++m)
                            if (S & (1 << m))
                                best = fmaxf(best, dp[S ^ (1 << m)] + A[r * 6 + m]);
                        dp[S] = best;
                    }
                }
            }
            cost = A[36] - 2.0f * dp[63];
        }
    }

    // ---- 5) reduce the 16 costs (first warp) and atomicAdd once
    if (t < 32) {
#pragma unroll
        for (int o = 8; o > 0; o >>= 1)
            cost += __shfl_down_sync(0xffffffffu, cost, o);
        if (t == 0) atomicAdd(out, cost);
    }
}

extern "C" void kernel_launch(void* const* d_in, const int* in_sizes, int n_in,
                              void* d_out, int out_size)
{
    const float* preds   = (const float*)d_in[0];
    const float* targets = (const float*)d_in[1];
    const int B = in_sizes[0] / 384;   // 6 * 64 floats per batch

    cudaMemsetAsync(d_out, 0, sizeof(float));
    const long long threads = (long long)B * 8;
    const int grid = (int)((threads + BLOCK - 1) / BLOCK);
    emd_kernel<<<grid, BLOCK>>>(preds, targets, (float*)d_out, B);
}